// round 12
// baseline (speedup 1.0000x reference)
#include <cuda_runtime.h>

// HSMNet feature-volume, 4 scales fused — R5 geometry, THREADS=512 probe.
// out[bc,d,h,w] = (w>=d) ? |ref[bc,h,w] - tgt[bc,h,w-d]| : 0
// Scales: s0 D=6 H=12 W=20 | s1 D=12 H=24 W=40 | s2 D=24 H=48 W=80 | s3 D=48 H=96 W=160
//
// Coalescing invariant: consecutive threads own consecutive w-quads -> every
// LDG.128 / STG.128 is a dense 512B warp transaction.
// s2/s3: 8(d) x 4(w) tile/thread.  s1: 4x4.  s0: scalar fallback.
// Uniform __stcs streaming stores (best measured policy).
//
// R12 delta (single variable): block size 256 -> 512. Only unexplored
// launch-shape knob; everything else byte-identical to the 33.2us kernel.

namespace {

constexpr int BC = 64;

constexpr int G0 = BC * 6 * 12 * 20 / 4;             //  23040 (float4 elems)
constexpr int G1 = BC * (12 / 4) * 24 * (40 / 4);    //  46080 (4x4 tiles)
constexpr int G2 = BC * (24 / 8) * 48 * (80 / 4);    // 184320 (8x4 tiles)
constexpr int G3 = BC * (48 / 8) * 96 * (160 / 4);   // 1474560 (8x4 tiles)

constexpr int CA = G0;           //   23040
constexpr int CB = CA + G1;      //   69120
constexpr int CC = CB + G2;      //  253440
constexpr int CD = CC + G3;      // 1728000 total threads

constexpr int O0 = 0;
constexpr int O1 = O0 + BC * 6 * 12 * 20;     //   92160
constexpr int O2 = O1 + BC * 12 * 24 * 40;    //  829440
constexpr int O3 = O2 + BC * 24 * 48 * 80;    // 6727680

constexpr int THREADS = 512;
constexpr int BLOCKS  = CD / THREADS;         // 3375 exact

__device__ __forceinline__ void st4(float* p, float a, float b, float c, float d) {
    __stcs(reinterpret_cast<float4*>(p), make_float4(a, b, c, d));
}

// scale-0 fallback: one float4 of output per thread
template <int D, int H, int W>
__device__ __forceinline__ void feat_vol_elem(const float* __restrict__ ref,
                                              const float* __restrict__ tgt,
                                              float* __restrict__ out, int i) {
    constexpr int W4 = W / 4;
    int w4 = i % W4;
    int t  = i / W4;
    int h  = t % H;  t /= H;
    int d  = t % D;
    int bc = t / D;

    const int base = (bc * H + h) * W;
    const int w0   = w4 * 4;
    const float4 r = *reinterpret_cast<const float4*>(ref + base + w0);
    const float* __restrict__ trow = tgt + base;
    float rv[4] = {r.x, r.y, r.z, r.w};
    float o[4];
#pragma unroll
    for (int j = 0; j < 4; ++j) {
        const int tw = w0 + j - d;
        o[j] = (tw >= 0) ? fabsf(rv[j] - trow[tw]) : 0.0f;
    }
    st4(out + (size_t)i * 4, o[0], o[1], o[2], o[3]);
}

// DT(d) x 4(w) tile per thread.  DT in {4, 8}.
// tgt window: trow[e-DT .. e+3], covered by (DT/4 + 1) aligned quads.
template <int D, int H, int W, int DT>
__device__ __forceinline__ void feat_vol_tile(const float* __restrict__ ref,
                                              const float* __restrict__ tgt,
                                              float* __restrict__ out, int i) {
    constexpr int W4 = W / 4;
    constexpr int DG = D / DT;
    constexpr int OSTRIDE = H * W;
    constexpr int NQ = DT / 4 + 1;      // tgt quads
    constexpr int NW = NQ * 4;          // window floats

    int w4 = i % W4;
    int t  = i / W4;
    int h  = t % H;  t /= H;
    int dg = t % DG;
    int bc = t / DG;

    const int w0 = w4 * 4;
    const int d0 = dg * DT;
    const int e  = w0 - d0;                       // multiple of 4
    const int base = (bc * H + h) * W;
    float* __restrict__ orow = out + ((size_t)(bc * D + d0) * H + h) * W + w0;

    if (e <= -4) {                                // max tw = e+3 < 0: all masked
#pragma unroll
        for (int k = 0; k < DT; ++k)
            st4(orow + k * OSTRIDE, 0.f, 0.f, 0.f, 0.f);
        return;
    }

    const float4 r = *reinterpret_cast<const float4*>(ref + base + w0);
    const float rv[4] = {r.x, r.y, r.z, r.w};

    float twin[NW];                               // trow[e-DT .. e+3]
#pragma unroll
    for (int q = 0; q < NQ; ++q) {
        const int off = e - DT + q * 4;
        if (off >= 0) {
            const float4 v = *reinterpret_cast<const float4*>(tgt + base + off);
            twin[q * 4 + 0] = v.x; twin[q * 4 + 1] = v.y;
            twin[q * 4 + 2] = v.z; twin[q * 4 + 3] = v.w;
        } else {
            twin[q * 4 + 0] = twin[q * 4 + 1] = 0.f;
            twin[q * 4 + 2] = twin[q * 4 + 3] = 0.f;
        }
    }

#pragma unroll
    for (int k = 0; k < DT; ++k) {                // d = d0 + k
        float o[4];
#pragma unroll
        for (int j = 0; j < 4; ++j) {             // w = w0 + j
            const float v = fabsf(rv[j] - twin[j - k + DT]);
            o[j] = (e + j - k >= 0) ? v : 0.f;
        }
        st4(orow + k * OSTRIDE, o[0], o[1], o[2], o[3]);
    }
}

__global__ void __launch_bounds__(THREADS)
hsmnet_featvol_kernel(const float* __restrict__ c40, const float* __restrict__ c41,
                      const float* __restrict__ c30, const float* __restrict__ c31,
                      const float* __restrict__ c20, const float* __restrict__ c21,
                      const float* __restrict__ c10, const float* __restrict__ c11,
                      float* __restrict__ out) {
    const int gid = blockIdx.x * THREADS + threadIdx.x;

    if (gid < CA) {
        feat_vol_elem<6, 12, 20>(c40, c41, out + O0, gid);
    } else if (gid < CB) {
        feat_vol_tile<12, 24, 40, 4>(c30, c31, out + O1, gid - CA);
    } else if (gid < CC) {
        feat_vol_tile<24, 48, 80, 8>(c20, c21, out + O2, gid - CB);
    } else {
        feat_vol_tile<48, 96, 160, 8>(c10, c11, out + O3, gid - CC);
    }
}

}  // namespace

extern "C" void kernel_launch(void* const* d_in, const int* in_sizes, int n_in,
                              void* d_out, int out_size) {
    const float* c40 = (const float*)d_in[0];
    const float* c41 = (const float*)d_in[1];
    const float* c30 = (const float*)d_in[2];
    const float* c31 = (const float*)d_in[3];
    const float* c20 = (const float*)d_in[4];
    const float* c21 = (const float*)d_in[5];
    const float* c10 = (const float*)d_in[6];
    const float* c11 = (const float*)d_in[7];
    float* out = (float*)d_out;

    hsmnet_featvol_kernel<<<BLOCKS, THREADS>>>(c40, c41, c30, c31,
                                               c20, c21, c10, c11, out);
}

// round 13
// speedup vs baseline: 1.0491x; 1.0491x over previous
#include <cuda_runtime.h>

// HSMNet feature-volume, 4 scales fused — SESSION FINAL (best measured: 33.2us).
// out[bc,d,h,w] = (w>=d) ? |ref[bc,h,w] - tgt[bc,h,w-d]| : 0
// Scales: s0 D=6 H=12 W=20 | s1 D=12 H=24 W=40 | s2 D=24 H=48 W=80 | s3 D=48 H=96 W=160
//
// Coalescing invariant: consecutive threads own consecutive w-quads -> every
// LDG.128 / STG.128 is a dense 512B warp transaction.
// s2/s3: 8(d) x 4(w) tile/thread.  s1: 4x4.  s0: scalar fallback.
// Uniform __stcs streaming stores; 256-thread CTAs; natural multi-wave launch.
//
// Measured floor: the mandatory 216MB output write stream drains at
// ~4.8TB/s DRAM (~6.2TB/s effective incl. L2-absorbed lines) -> ~34us.
// Falsified levers: sparse-lane wide tiles (-60%), bigger tiles (neutral),
// resident-prefix stores (neutral), evict_last+STG.256 (-2%), persistent
// single-wave loop (-11%), 512-thread CTAs (-1%).

namespace {

constexpr int BC = 64;

constexpr int G0 = BC * 6 * 12 * 20 / 4;             //  23040 (float4 elems)
constexpr int G1 = BC * (12 / 4) * 24 * (40 / 4);    //  46080 (4x4 tiles)
constexpr int G2 = BC * (24 / 8) * 48 * (80 / 4);    // 184320 (8x4 tiles)
constexpr int G3 = BC * (48 / 8) * 96 * (160 / 4);   // 1474560 (8x4 tiles)

constexpr int CA = G0;           //   23040
constexpr int CB = CA + G1;      //   69120
constexpr int CC = CB + G2;      //  253440
constexpr int CD = CC + G3;      // 1728000 total threads

constexpr int O0 = 0;
constexpr int O1 = O0 + BC * 6 * 12 * 20;     //   92160
constexpr int O2 = O1 + BC * 12 * 24 * 40;    //  829440
constexpr int O3 = O2 + BC * 24 * 48 * 80;    // 6727680

constexpr int THREADS = 256;
constexpr int BLOCKS  = CD / THREADS;         // 6750 exact

__device__ __forceinline__ void st4(float* p, float a, float b, float c, float d) {
    __stcs(reinterpret_cast<float4*>(p), make_float4(a, b, c, d));
}

// scale-0 fallback: one float4 of output per thread
template <int D, int H, int W>
__device__ __forceinline__ void feat_vol_elem(const float* __restrict__ ref,
                                              const float* __restrict__ tgt,
                                              float* __restrict__ out, int i) {
    constexpr int W4 = W / 4;
    int w4 = i % W4;
    int t  = i / W4;
    int h  = t % H;  t /= H;
    int d  = t % D;
    int bc = t / D;

    const int base = (bc * H + h) * W;
    const int w0   = w4 * 4;
    const float4 r = *reinterpret_cast<const float4*>(ref + base + w0);
    const float* __restrict__ trow = tgt + base;
    float rv[4] = {r.x, r.y, r.z, r.w};
    float o[4];
#pragma unroll
    for (int j = 0; j < 4; ++j) {
        const int tw = w0 + j - d;
        o[j] = (tw >= 0) ? fabsf(rv[j] - trow[tw]) : 0.0f;
    }
    st4(out + (size_t)i * 4, o[0], o[1], o[2], o[3]);
}

// DT(d) x 4(w) tile per thread.  DT in {4, 8}.
// tgt window: trow[e-DT .. e+3], covered by (DT/4 + 1) aligned quads.
template <int D, int H, int W, int DT>
__device__ __forceinline__ void feat_vol_tile(const float* __restrict__ ref,
                                              const float* __restrict__ tgt,
                                              float* __restrict__ out, int i) {
    constexpr int W4 = W / 4;
    constexpr int DG = D / DT;
    constexpr int OSTRIDE = H * W;
    constexpr int NQ = DT / 4 + 1;      // tgt quads
    constexpr int NW = NQ * 4;          // window floats

    int w4 = i % W4;
    int t  = i / W4;
    int h  = t % H;  t /= H;
    int dg = t % DG;
    int bc = t / DG;

    const int w0 = w4 * 4;
    const int d0 = dg * DT;
    const int e  = w0 - d0;                       // multiple of 4
    const int base = (bc * H + h) * W;
    float* __restrict__ orow = out + ((size_t)(bc * D + d0) * H + h) * W + w0;

    if (e <= -4) {                                // max tw = e+3 < 0: all masked
#pragma unroll
        for (int k = 0; k < DT; ++k)
            st4(orow + k * OSTRIDE, 0.f, 0.f, 0.f, 0.f);
        return;
    }

    const float4 r = *reinterpret_cast<const float4*>(ref + base + w0);
    const float rv[4] = {r.x, r.y, r.z, r.w};

    float twin[NW];                               // trow[e-DT .. e+3]
#pragma unroll
    for (int q = 0; q < NQ; ++q) {
        const int off = e - DT + q * 4;
        if (off >= 0) {
            const float4 v = *reinterpret_cast<const float4*>(tgt + base + off);
            twin[q * 4 + 0] = v.x; twin[q * 4 + 1] = v.y;
            twin[q * 4 + 2] = v.z; twin[q * 4 + 3] = v.w;
        } else {
            twin[q * 4 + 0] = twin[q * 4 + 1] = 0.f;
            twin[q * 4 + 2] = twin[q * 4 + 3] = 0.f;
        }
    }

#pragma unroll
    for (int k = 0; k < DT; ++k) {                // d = d0 + k
        float o[4];
#pragma unroll
        for (int j = 0; j < 4; ++j) {             // w = w0 + j
            const float v = fabsf(rv[j] - twin[j - k + DT]);
            o[j] = (e + j - k >= 0) ? v : 0.f;
        }
        st4(orow + k * OSTRIDE, o[0], o[1], o[2], o[3]);
    }
}

__global__ void __launch_bounds__(THREADS)
hsmnet_featvol_kernel(const float* __restrict__ c40, const float* __restrict__ c41,
                      const float* __restrict__ c30, const float* __restrict__ c31,
                      const float* __restrict__ c20, const float* __restrict__ c21,
                      const float* __restrict__ c10, const float* __restrict__ c11,
                      float* __restrict__ out) {
    const int gid = blockIdx.x * THREADS + threadIdx.x;

    if (gid < CA) {
        feat_vol_elem<6, 12, 20>(c40, c41, out + O0, gid);
    } else if (gid < CB) {
        feat_vol_tile<12, 24, 40, 4>(c30, c31, out + O1, gid - CA);
    } else if (gid < CC) {
        feat_vol_tile<24, 48, 80, 8>(c20, c21, out + O2, gid - CB);
    } else {
        feat_vol_tile<48, 96, 160, 8>(c10, c11, out + O3, gid - CC);
    }
}

}  // namespace

extern "C" void kernel_launch(void* const* d_in, const int* in_sizes, int n_in,
                              void* d_out, int out_size) {
    const float* c40 = (const float*)d_in[0];
    const float* c41 = (const float*)d_in[1];
    const float* c30 = (const float*)d_in[2];
    const float* c31 = (const float*)d_in[3];
    const float* c20 = (const float*)d_in[4];
    const float* c21 = (const float*)d_in[5];
    const float* c10 = (const float*)d_in[6];
    const float* c11 = (const float*)d_in[7];
    float* out = (float*)d_out;

    hsmnet_featvol_kernel<<<BLOCKS, THREADS>>>(c40, c41, c30, c31,
                                               c20, c21, c10, c11, out);
}